// round 1
// baseline (speedup 1.0000x reference)
#include <cuda_runtime.h>
#include <cuda_bf16.h>

// Problem constants
#define NB   4096      // batch
#define NK   50        // neighbors
#define ND   64        // embedding dim
#define NL   3         // layers

// Scratch (device globals — no allocation allowed)
__device__ float g_U[NB * ND];   // final user embeddings
__device__ float g_V[NB * ND];   // gathered item embeddings

// ----------------------------------------------------------------------------
// Kernel A: fused gather + weighted neighbor sums (w, w^2, w^3) + 3-layer MLP
// Block: 256 threads = 4 batch rows x 64 dims
// ----------------------------------------------------------------------------
__global__ __launch_bounds__(256)
void fused_gather_mlp(const int* __restrict__ user_ids,
                      const int* __restrict__ item_ids,
                      const int* __restrict__ social_neighbors,
                      const float* __restrict__ attention_mask,
                      const float* __restrict__ user_table,
                      const float* __restrict__ item_table,
                      const float* __restrict__ Ws,
                      const float* __restrict__ bs)
{
    __shared__ float s_x[4][ND];
    __shared__ float s_xin[4][ND];
    __shared__ float s_W[ND][ND + 1];   // +1 pad -> conflict-free s_W[d][i]
    __shared__ float s_b[ND];
    __shared__ int   s_nbr[4][NK];
    __shared__ float s_msk[4][NK];

    const int tid = threadIdx.x;
    const int r   = tid >> 6;     // row within block (0..3)
    const int d   = tid & 63;     // dim (0..63)
    const int b   = blockIdx.x * 4 + r;

    // Cooperative load of neighbor indices + masks
    for (int i = tid; i < 4 * NK; i += 256) {
        int rr = i / NK, kk = i - rr * NK;
        int bb = blockIdx.x * 4 + rr;
        s_nbr[rr][kk] = social_neighbors[bb * NK + kk];
        s_msk[rr][kk] = attention_mask[bb * NK + kk];
    }
    __syncthreads();

    // user + item embedding gather (coalesced per warp across d)
    float u = user_table[(long)user_ids[b] * ND + d];
    g_V[b * ND + d] = item_table[(long)item_ids[b] * ND + d];

    // One pass over neighbors computes all 3 layers' weighted sums
    float a1 = 0.f, a2 = 0.f, a3 = 0.f;
#pragma unroll 5
    for (int k = 0; k < NK; k++) {
        int   n = s_nbr[r][k];
        float w = s_msk[r][k];
        float v = user_table[(long)n * ND + d];
        float wv = w * v;
        a1 += wv;
        wv *= w;
        a2 += wv;
        wv *= w;
        a3 += wv;
    }
    const float inv = 1.0f / (float)NK;
    float sums[3];
    sums[0] = a1 * inv; sums[1] = a2 * inv; sums[2] = a3 * inv;

    s_x[r][d] = u;
    float y = 0.f;

#pragma unroll
    for (int l = 0; l < NL; l++) {
        __syncthreads();   // guards s_W reuse + s_x updates
        // stage W_l into shared
        const float* W = Ws + l * ND * ND;
        for (int i = tid; i < ND * ND; i += 256)
            s_W[i >> 6][i & 63] = W[i];
        if (tid < ND) s_b[tid] = bs[l * ND + tid];
        s_xin[r][d] = s_x[r][d] + sums[l];
        __syncthreads();

        float acc = s_b[d];
#pragma unroll
        for (int i = 0; i < ND; i++)
            acc = fmaf(s_xin[r][i], s_W[d][i], acc);   // broadcast * conflict-free
        y = fmaxf(acc, 0.f);
        __syncthreads();
        s_x[r][d] = y;
    }

    g_U[b * ND + d] = y;
}

// ----------------------------------------------------------------------------
// Kernel B: scores = U @ V^T  (M=N=4096, K=64), fp32 via packed fma.rn.f32x2
// 128x128 block tile, 256 threads, 8x8 thread tile, k-major shared tiles.
// ----------------------------------------------------------------------------
__device__ __forceinline__ unsigned long long dup2(float x) {
    unsigned long long r;
    asm("mov.b64 %0, {%1, %1};" : "=l"(r) : "f"(x));
    return r;
}
__device__ __forceinline__ void ffma2(unsigned long long& d,
                                      unsigned long long a,
                                      unsigned long long b) {
    asm("fma.rn.f32x2 %0, %1, %2, %0;" : "+l"(d) : "l"(a), "l"(b));
}

union F4U { float4 f; unsigned long long u[2]; };

__global__ __launch_bounds__(256, 2)
void score_gemm(float* __restrict__ C)
{
    __shared__ float sA[32][128];   // A[k][m]
    __shared__ float sB[32][128];   // B[k][n]

    const int tid = threadIdx.x;
    const int tx  = tid & 15;       // 0..15 -> n groups
    const int ty  = tid >> 4;       // 0..15 -> m groups
    const int bM  = blockIdx.y * 128;
    const int bN  = blockIdx.x * 128;

    unsigned long long acc[8][4];
#pragma unroll
    for (int i = 0; i < 8; i++)
#pragma unroll
        for (int j = 0; j < 4; j++) acc[i][j] = 0ull;

#pragma unroll
    for (int kt = 0; kt < 2; kt++) {
        // Stage 128x32 tiles (coalesced float4 global reads, transposed store)
#pragma unroll
        for (int c = 0; c < 4; c++) {
            int idx = tid + c * 256;      // 0..1023
            int m   = idx >> 3;           // 0..127
            int kq  = idx & 7;            // 0..7 (float4 chunks of the 32-k slab)
            float4 va = *(const float4*)&g_U[(bM + m) * ND + kt * 32 + kq * 4];
            sA[kq * 4 + 0][m] = va.x;
            sA[kq * 4 + 1][m] = va.y;
            sA[kq * 4 + 2][m] = va.z;
            sA[kq * 4 + 3][m] = va.w;
            float4 vb = *(const float4*)&g_V[(bN + m) * ND + kt * 32 + kq * 4];
            sB[kq * 4 + 0][m] = vb.x;
            sB[kq * 4 + 1][m] = vb.y;
            sB[kq * 4 + 2][m] = vb.z;
            sB[kq * 4 + 3][m] = vb.w;
        }
        __syncthreads();

#pragma unroll
        for (int k = 0; k < 32; k++) {
            float4 a0 = *(const float4*)&sA[k][ty * 8];
            float4 a1 = *(const float4*)&sA[k][ty * 8 + 4];
            F4U b0, b1;
            b0.f = *(const float4*)&sB[k][tx * 4];
            b1.f = *(const float4*)&sB[k][64 + tx * 4];
            unsigned long long bb0 = b0.u[0], bb1 = b0.u[1];
            unsigned long long bb2 = b1.u[0], bb3 = b1.u[1];
            float a[8] = {a0.x, a0.y, a0.z, a0.w, a1.x, a1.y, a1.z, a1.w};
#pragma unroll
            for (int i = 0; i < 8; i++) {
                unsigned long long ad = dup2(a[i]);
                ffma2(acc[i][0], ad, bb0);
                ffma2(acc[i][1], ad, bb1);
                ffma2(acc[i][2], ad, bb2);
                ffma2(acc[i][3], ad, bb3);
            }
        }
        __syncthreads();
    }

    // Epilogue: coalesced float4 stores
#pragma unroll
    for (int i = 0; i < 8; i++) {
        int row = bM + ty * 8 + i;
        F4U o0, o1;
        o0.u[0] = acc[i][0]; o0.u[1] = acc[i][1];
        o1.u[0] = acc[i][2]; o1.u[1] = acc[i][3];
        *(float4*)&C[(long)row * NB + bN + tx * 4]      = o0.f;
        *(float4*)&C[(long)row * NB + bN + 64 + tx * 4] = o1.f;
    }
}

// ----------------------------------------------------------------------------
extern "C" void kernel_launch(void* const* d_in, const int* in_sizes, int n_in,
                              void* d_out, int out_size)
{
    const int*   user_ids         = (const int*)  d_in[0];
    const int*   item_ids         = (const int*)  d_in[1];
    const int*   social_neighbors = (const int*)  d_in[2];
    const float* attention_mask   = (const float*)d_in[3];
    const float* user_table       = (const float*)d_in[4];
    const float* item_table       = (const float*)d_in[5];
    const float* Ws               = (const float*)d_in[6];
    const float* bs               = (const float*)d_in[7];
    float* out = (float*)d_out;

    fused_gather_mlp<<<NB / 4, 256>>>(user_ids, item_ids, social_neighbors,
                                      attention_mask, user_table, item_table,
                                      Ws, bs);

    dim3 grid(NB / 128, NB / 128);
    score_gemm<<<grid, 256>>>(out);
}

// round 4
// speedup vs baseline: 1.3294x; 1.3294x over previous
#include <cuda_runtime.h>
#include <cuda_bf16.h>
#include <cstdint>

#define NB   4096
#define NK   50
#define ND   64
#define NL   3

// ---------------- scratch (device globals; no allocation allowed) -----------
__device__ __nv_bfloat16 g_Uh[NB * ND];
__device__ __nv_bfloat16 g_Ul[NB * ND];
__device__ __nv_bfloat16 g_Vh[NB * ND];
__device__ __nv_bfloat16 g_Vl[NB * ND];

#define SWZ128(o) ((uint32_t)(o) ^ (((uint32_t)(o) >> 3) & 0x70u))

__device__ __forceinline__ uint32_t smem_u32(const void* p) {
    uint32_t a;
    asm("{ .reg .u64 t; cvta.to.shared.u64 t, %1; cvt.u32.u64 %0, t; }"
        : "=r"(a) : "l"(p));
    return a;
}

__device__ __forceinline__ void ldm_x4(uint32_t* r, uint32_t addr) {
    asm volatile("ldmatrix.sync.aligned.m8n8.x4.shared.b16 {%0,%1,%2,%3}, [%4];"
                 : "=r"(r[0]), "=r"(r[1]), "=r"(r[2]), "=r"(r[3]) : "r"(addr));
}
__device__ __forceinline__ void ldm_x2(uint32_t* r, uint32_t addr) {
    asm volatile("ldmatrix.sync.aligned.m8n8.x2.shared.b16 {%0,%1}, [%2];"
                 : "=r"(r[0]), "=r"(r[1]) : "r"(addr));
}
__device__ __forceinline__ void mma16816(float* d, const uint32_t* a,
                                         const uint32_t* b) {
    asm volatile(
        "mma.sync.aligned.m16n8k16.row.col.f32.bf16.bf16.f32 "
        "{%0,%1,%2,%3}, {%4,%5,%6,%7}, {%8,%9}, {%0,%1,%2,%3};"
        : "+f"(d[0]), "+f"(d[1]), "+f"(d[2]), "+f"(d[3])
        : "r"(a[0]), "r"(a[1]), "r"(a[2]), "r"(a[3]), "r"(b[0]), "r"(b[1]));
}

// ---------------------------------------------------------------------------
// Kernel A: gather + weighted neighbor sums (w, w^2, w^3) + 3-layer MLP
//           emits bf16 hi/lo split of U and V. Dynamic smem (63.8 KB).
// Block: 256 threads = 16 rows x 16 lanes (float4 each).
// ---------------------------------------------------------------------------
#define GA_SMEM ((NL * ND * 68 + NL * ND + 16 * 64 + 16 * 64 + 16 * 64) * 4)

__global__ __launch_bounds__(256)
void gather_mlp(const int* __restrict__ user_ids,
                const int* __restrict__ item_ids,
                const int* __restrict__ nbr,
                const float* __restrict__ mask,
                const float* __restrict__ ut,
                const float* __restrict__ itab,
                const float* __restrict__ Ws,
                const float* __restrict__ bsv)
{
    extern __shared__ float dsm[];
    float* s_W = dsm;                        // [l][in][68] transposed, padded
    float* s_b = s_W + NL * ND * 68;         // [l][64]
    float* s_x = s_b + NL * ND;              // [16][64]
    float* s_m = s_x + 16 * 64;              // [16][64] (NK=50 used)
    int*   s_n = (int*)(s_m + 16 * 64);      // [16][64]

    const int tid = threadIdx.x;
    const int r = tid >> 4;          // 0..15
    const int q = tid & 15;          // 0..15 (float4 lane)
    const int b0 = blockIdx.x * 16;
    const int b = b0 + r;

    for (int i = tid; i < 16 * NK; i += 256) {
        int rr = i / NK, kk = i - rr * NK;
        int g = (b0 + rr) * NK + kk;
        s_n[rr * 64 + kk] = nbr[g];
        s_m[rr * 64 + kk] = mask[g];
    }
    // stage W transposed: s_W[l][in][out] = Ws[l][out][in]
    for (int i = tid; i < NL * ND * ND; i += 256) {
        int l = i >> 12, rem = i & 4095;
        int o = rem >> 6, in_ = rem & 63;
        s_W[(l * ND + in_) * 68 + o] = Ws[i];
    }
    for (int i = tid; i < NL * ND; i += 256)
        s_b[i] = bsv[i];
    __syncthreads();

    // item gather -> bf16 split
    {
        float4 v = *(const float4*)&itab[(long)item_ids[b] * ND + q * 4];
        float f[4] = {v.x, v.y, v.z, v.w};
        __nv_bfloat16 h0 = __float2bfloat16(f[0]), h1 = __float2bfloat16(f[1]);
        __nv_bfloat16 h2 = __float2bfloat16(f[2]), h3 = __float2bfloat16(f[3]);
        __nv_bfloat162 h01(h0, h1), h23(h2, h3);
        __nv_bfloat162 l01(__float2bfloat16(f[0] - __bfloat162float(h0)),
                           __float2bfloat16(f[1] - __bfloat162float(h1)));
        __nv_bfloat162 l23(__float2bfloat16(f[2] - __bfloat162float(h2)),
                           __float2bfloat16(f[3] - __bfloat162float(h3)));
        int off = b * ND + q * 4;
        *(__nv_bfloat162*)&g_Vh[off] = h01; *(__nv_bfloat162*)&g_Vh[off + 2] = h23;
        *(__nv_bfloat162*)&g_Vl[off] = l01; *(__nv_bfloat162*)&g_Vl[off + 2] = l23;
    }

    float4 u = *(const float4*)&ut[(long)user_ids[b] * ND + q * 4];

    // one pass over neighbors: weighted sums for w, w^2, w^3
    float a1x=0,a1y=0,a1z=0,a1w=0, a2x=0,a2y=0,a2z=0,a2w=0, a3x=0,a3y=0,a3z=0,a3w=0;
#pragma unroll
    for (int kb = 0; kb < NK; kb += 10) {
        float4 vv[10]; float ww[10];
#pragma unroll
        for (int j = 0; j < 10; j++) {
            int n = s_n[r * 64 + kb + j];
            ww[j] = s_m[r * 64 + kb + j];
            vv[j] = *(const float4*)&ut[(long)n * ND + q * 4];
        }
#pragma unroll
        for (int j = 0; j < 10; j++) {
            float w = ww[j];
            float tx = w * vv[j].x, ty = w * vv[j].y, tz = w * vv[j].z, tw = w * vv[j].w;
            a1x += tx; a1y += ty; a1z += tz; a1w += tw;
            tx *= w; ty *= w; tz *= w; tw *= w;
            a2x += tx; a2y += ty; a2z += tz; a2w += tw;
            tx *= w; ty *= w; tz *= w; tw *= w;
            a3x += tx; a3y += ty; a3z += tz; a3w += tw;
        }
    }
    const float inv = 1.0f / (float)NK;
    float4 sums[3];
    sums[0] = make_float4(a1x*inv, a1y*inv, a1z*inv, a1w*inv);
    sums[1] = make_float4(a2x*inv, a2y*inv, a2z*inv, a2w*inv);
    sums[2] = make_float4(a3x*inv, a3y*inv, a3z*inv, a3w*inv);

    float4 x = u;
#pragma unroll
    for (int l = 0; l < NL; l++) {
        float4 xin = make_float4(x.x + sums[l].x, x.y + sums[l].y,
                                 x.z + sums[l].z, x.w + sums[l].w);
        *(float4*)&s_x[r * 64 + q * 4] = xin;
        __syncthreads();
        float4 acc = *(const float4*)&s_b[l * 64 + q * 4];
#pragma unroll
        for (int i = 0; i < ND; i++) {
            float xi = s_x[r * 64 + i];
            float4 w4 = *(const float4*)&s_W[(l * ND + i) * 68 + q * 4];
            acc.x = fmaf(xi, w4.x, acc.x);
            acc.y = fmaf(xi, w4.y, acc.y);
            acc.z = fmaf(xi, w4.z, acc.z);
            acc.w = fmaf(xi, w4.w, acc.w);
        }
        x = make_float4(fmaxf(acc.x, 0.f), fmaxf(acc.y, 0.f),
                        fmaxf(acc.z, 0.f), fmaxf(acc.w, 0.f));
        __syncthreads();
    }

    // U bf16 split
    {
        float f[4] = {x.x, x.y, x.z, x.w};
        __nv_bfloat16 h0 = __float2bfloat16(f[0]), h1 = __float2bfloat16(f[1]);
        __nv_bfloat16 h2 = __float2bfloat16(f[2]), h3 = __float2bfloat16(f[3]);
        __nv_bfloat162 h01(h0, h1), h23(h2, h3);
        __nv_bfloat162 l01(__float2bfloat16(f[0] - __bfloat162float(h0)),
                           __float2bfloat16(f[1] - __bfloat162float(h1)));
        __nv_bfloat162 l23(__float2bfloat16(f[2] - __bfloat162float(h2)),
                           __float2bfloat16(f[3] - __bfloat162float(h3)));
        int off = b * ND + q * 4;
        *(__nv_bfloat162*)&g_Uh[off] = h01; *(__nv_bfloat162*)&g_Uh[off + 2] = h23;
        *(__nv_bfloat162*)&g_Ul[off] = l01; *(__nv_bfloat162*)&g_Ul[off + 2] = l23;
    }
}

// ---------------------------------------------------------------------------
// Kernel B: C = U @ V^T via mma.sync m16n8k16 bf16, hi/lo split (3 products).
// CTA 128x128, 8 warps (2m x 4n), warp tile 64x32. K=64 smem-resident.
// Dynamic smem 64 KB: Ah | Al | Bh | Bl, 128 rows x 128B each, XOR-swizzled.
// ---------------------------------------------------------------------------
#define SM_AH 0
#define SM_AL 16384
#define SM_BH 32768
#define SM_BL 49152
#define SM_GEMM 65536

__global__ __launch_bounds__(256)
void score_gemm_mma(float* __restrict__ C)
{
    extern __shared__ char smem[];
    const uint32_t sb = smem_u32(smem);
    const int tid = threadIdx.x;
    const int wid = tid >> 5, lid = tid & 31;
    const int bM = blockIdx.y * 128;
    const int bN = blockIdx.x * 128;

    // ---- stage all four 128x64 bf16 tiles (swizzled 16B chunks) ----
    const uint4* Uh4 = (const uint4*)g_Uh;
    const uint4* Ul4 = (const uint4*)g_Ul;
    const uint4* Vh4 = (const uint4*)g_Vh;
    const uint4* Vl4 = (const uint4*)g_Vl;
#pragma unroll
    for (int c = 0; c < 4; c++) {
        int i = tid + c * 256;          // 0..1023
        int row = i >> 3, ch = i & 7;
        uint32_t sw = SWZ128(row * 128 + ch * 16);
        *(uint4*)(smem + SM_AH + sw) = Uh4[(bM + row) * 8 + ch];
        *(uint4*)(smem + SM_AL + sw) = Ul4[(bM + row) * 8 + ch];
        *(uint4*)(smem + SM_BH + sw) = Vh4[(bN + row) * 8 + ch];
        *(uint4*)(smem + SM_BL + sw) = Vl4[(bN + row) * 8 + ch];
    }
    __syncthreads();

    const int mw = (wid & 1) * 64;       // warp m offset
    const int nw = (wid >> 1) * 32;      // warp n offset
    const int t8 = lid >> 3, r8 = lid & 7;

    float acc[4][4][4];
#pragma unroll
    for (int mi = 0; mi < 4; mi++)
#pragma unroll
        for (int ni = 0; ni < 4; ni++)
#pragma unroll
            for (int j = 0; j < 4; j++) acc[mi][ni][j] = 0.f;

    const uint32_t aOffs[3] = {SM_AH, SM_AH, SM_AL};
    const uint32_t bOffs[3] = {SM_BH, SM_BL, SM_BH};

#pragma unroll
    for (int p = 0; p < 3; p++) {
        const uint32_t aBase = sb + aOffs[p];
        const uint32_t bBase = sb + bOffs[p];
#pragma unroll
        for (int s = 0; s < 4; s++) {    // k-steps of 16
            uint32_t af[4][4], bf[4][2];
#pragma unroll
            for (int mi = 0; mi < 4; mi++) {
                int row = mw + mi * 16 + r8 + (t8 & 1) * 8;
                int ch = 2 * s + (t8 >> 1);
                ldm_x4(af[mi], aBase + SWZ128(row * 128 + ch * 16));
            }
#pragma unroll
            for (int ni = 0; ni < 4; ni++) {
                int row = nw + ni * 8 + r8;
                int ch = 2 * s + (t8 & 1);
                ldm_x2(bf[ni], bBase + SWZ128(row * 128 + ch * 16));
            }
#pragma unroll
            for (int mi = 0; mi < 4; mi++)
#pragma unroll
                for (int ni = 0; ni < 4; ni++)
                    mma16816(acc[mi][ni], af[mi], bf[ni]);
        }
    }

    // ---- epilogue: direct float2 stores (coalesced 32B per quad-row) ----
    const int qr = lid >> 2;             // 0..7 row-in-tile
    const int qc = (lid & 3) * 2;        // col pair
#pragma unroll
    for (int mi = 0; mi < 4; mi++) {
        long row0 = bM + mw + mi * 16 + qr;
#pragma unroll
        for (int ni = 0; ni < 4; ni++) {
            long col = bN + nw + ni * 8 + qc;
            *(float2*)&C[row0 * NB + col] =
                make_float2(acc[mi][ni][0], acc[mi][ni][1]);
            *(float2*)&C[(row0 + 8) * NB + col] =
                make_float2(acc[mi][ni][2], acc[mi][ni][3]);
        }
    }
}

// ---------------------------------------------------------------------------
extern "C" void kernel_launch(void* const* d_in, const int* in_sizes, int n_in,
                              void* d_out, int out_size)
{
    const int*   user_ids         = (const int*)  d_in[0];
    const int*   item_ids         = (const int*)  d_in[1];
    const int*   social_neighbors = (const int*)  d_in[2];
    const float* attention_mask   = (const float*)d_in[3];
    const float* user_table       = (const float*)d_in[4];
    const float* item_table       = (const float*)d_in[5];
    const float* Ws               = (const float*)d_in[6];
    const float* bs               = (const float*)d_in[7];
    float* out = (float*)d_out;

    cudaFuncSetAttribute(gather_mlp,
                         cudaFuncAttributeMaxDynamicSharedMemorySize, GA_SMEM);
    cudaFuncSetAttribute(score_gemm_mma,
                         cudaFuncAttributeMaxDynamicSharedMemorySize, SM_GEMM);

    gather_mlp<<<NB / 16, 256, GA_SMEM>>>(user_ids, item_ids, social_neighbors,
                                          attention_mask, user_table,
                                          item_table, Ws, bs);

    dim3 grid(NB / 128, NB / 128);
    score_gemm_mma<<<grid, 256, SM_GEMM>>>(out);
}